// round 2
// baseline (speedup 1.0000x reference)
#include <cuda_runtime.h>
#include <math.h>

#define N_B 32
#define T_S 2048
#define H_S 1024
#define D_S 384
#define ROWS (N_B * T_S)   // 65536

// scratch (no allocations allowed)
__device__ float g_cb[N_B * H_S];       // c_proj + bias, per (n, k)
__device__ float g_scores[ROWS];        // attention logits, flat (n*T + t)
__device__ float g_weights[ROWS];       // softmax weights

__device__ __forceinline__ float to_tf32(float x) {
    asm("cvt.rna.tf32.f32 %0, %0;" : "+f"(x));
    return x;
}

__device__ __forceinline__ void mma8(float c[4], const unsigned a[4], unsigned b0, unsigned b1) {
    asm volatile(
        "mma.sync.aligned.m16n8k8.row.col.f32.tf32.tf32.f32 "
        "{%0,%1,%2,%3}, {%4,%5,%6,%7}, {%8,%9}, {%0,%1,%2,%3};\n"
        : "+f"(c[0]), "+f"(c[1]), "+f"(c[2]), "+f"(c[3])
        : "r"(a[0]), "r"(a[1]), "r"(a[2]), "r"(a[3]), "r"(b0), "r"(b1));
}

// ---------------------------------------------------------------------------
// Launch 1: cb[n][k] = bias[k] + sum_d cond[n][d] * Wc[d][k]; zero scores, out
// grid (32, 4), block 256
// ---------------------------------------------------------------------------
__global__ void prep_kernel(const float* __restrict__ cond,
                            const float* __restrict__ Wc,
                            const float* __restrict__ bias,
                            float* __restrict__ out) {
    const int n = blockIdx.x;
    const int k = blockIdx.y * 256 + threadIdx.x;
    float acc = bias[k];
    const float* cp = cond + n * D_S;
#pragma unroll 4
    for (int d = 0; d < D_S; d++)
        acc = fmaf(cp[d], Wc[d * H_S + k], acc);
    g_cb[n * H_S + k] = acc;
    out[n * H_S + k] = 0.0f;
    g_scores[n * T_S + blockIdx.y * 512 + threadIdx.x] = 0.0f;
    g_scores[n * T_S + blockIdx.y * 512 + threadIdx.x + 256] = 0.0f;
}

// ---------------------------------------------------------------------------
// Launch 2: scores[n,t] += sum_{k in chunk} v[k]*tanh(hp[t,k] + cb[n,k])
// hp tile = gru[128 rows] @ Wh[:, 128 cols], K = 1024, tf32 mma.sync
// grid (8 col-chunks, 512 row-tiles), block 256 (8 warps, 4x2 warp tiling)
// ---------------------------------------------------------------------------
#define SA_STR 17
#define SB_STR 132
#define KTILES 64   // 1024 / 16

__global__ __launch_bounds__(256, 2) void gemm_scores_kernel(
    const float* __restrict__ gru,
    const float* __restrict__ Wh,
    const float* __restrict__ v) {
    __shared__ float sA[2][128 * SA_STR];
    __shared__ float sB[2][16 * SB_STR];
    __shared__ float s_cb[128];
    __shared__ float s_v[128];

    const int tid = threadIdx.x;
    const int colBase = blockIdx.x * 128;
    const int rowBase = blockIdx.y * 128;
    const int n = rowBase >> 11;   // 2048 rows per batch, tiles never straddle n

    if (tid < 128) {
        s_cb[tid] = g_cb[n * H_S + colBase + tid];
        s_v[tid] = v[colBase + tid];
    }

    // global load mapping (coalesced float4)
    const int ar = tid >> 2;            // A row 0..63 (+64 second pass)
    const int ac = (tid & 3) << 2;      // A col group within 16-wide chunk
    const int bkr = tid >> 5;           // B k-row 0..7 (+8 second pass)
    const int bc = (tid & 31) << 2;     // B col group within 128-wide chunk

    const float* gA0 = gru + (size_t)(rowBase + ar) * H_S + ac;
    const float* gA1 = gA0 + (size_t)64 * H_S;
    const float* gB0 = Wh + (size_t)bkr * H_S + colBase + bc;
    const float* gB1 = gB0 + (size_t)8 * H_S;

    const int lane = tid & 31;
    const int wid = tid >> 5;
    const int row0 = (wid & 3) * 32;    // warp rows [row0, row0+32)
    const int col0 = (wid >> 2) * 64;   // warp cols [col0, col0+64)

    float acc[2][8][4];
#pragma unroll
    for (int i = 0; i < 2; i++)
#pragma unroll
        for (int j = 0; j < 8; j++)
#pragma unroll
            for (int q = 0; q < 4; q++) acc[i][j][q] = 0.0f;

    auto store_chunk = [&](int buf, float4 a0, float4 a1, float4 b0, float4 b1) {
        float* dA0 = &sA[buf][ar * SA_STR + ac];
        dA0[0] = to_tf32(a0.x); dA0[1] = to_tf32(a0.y);
        dA0[2] = to_tf32(a0.z); dA0[3] = to_tf32(a0.w);
        float* dA1 = &sA[buf][(ar + 64) * SA_STR + ac];
        dA1[0] = to_tf32(a1.x); dA1[1] = to_tf32(a1.y);
        dA1[2] = to_tf32(a1.z); dA1[3] = to_tf32(a1.w);
        float4 t0 = make_float4(to_tf32(b0.x), to_tf32(b0.y), to_tf32(b0.z), to_tf32(b0.w));
        float4 t1 = make_float4(to_tf32(b1.x), to_tf32(b1.y), to_tf32(b1.z), to_tf32(b1.w));
        *(float4*)&sB[buf][bkr * SB_STR + bc] = t0;
        *(float4*)&sB[buf][(bkr + 8) * SB_STR + bc] = t1;
    };

    auto compute = [&](int buf) {
#pragma unroll
        for (int ks = 0; ks < 2; ks++) {
            const int kk = ks * 8;
            unsigned aF[2][4];
#pragma unroll
            for (int mf = 0; mf < 2; mf++) {
                const float* a = &sA[buf][(row0 + mf * 16 + (lane >> 2)) * SA_STR + kk + (lane & 3)];
                aF[mf][0] = __float_as_uint(a[0]);
                aF[mf][1] = __float_as_uint(a[8 * SA_STR]);
                aF[mf][2] = __float_as_uint(a[4]);
                aF[mf][3] = __float_as_uint(a[8 * SA_STR + 4]);
            }
#pragma unroll
            for (int nf = 0; nf < 8; nf++) {
                const float* bp = &sB[buf][(kk + (lane & 3)) * SB_STR + col0 + nf * 8 + (lane >> 2)];
                unsigned b0 = __float_as_uint(bp[0]);
                unsigned b1 = __float_as_uint(bp[4 * SB_STR]);
                mma8(acc[0][nf], aF[0], b0, b1);
                mma8(acc[1][nf], aF[1], b0, b1);
            }
        }
    };

    // prologue: chunk 0
    float4 av0 = *(const float4*)gA0;
    float4 av1 = *(const float4*)gA1;
    float4 bv0 = *(const float4*)gB0;
    float4 bv1 = *(const float4*)gB1;
    store_chunk(0, av0, av1, bv0, bv1);
    __syncthreads();

#pragma unroll 1
    for (int kc = 1; kc < KTILES; kc++) {
        av0 = *(const float4*)(gA0 + kc * 16);
        av1 = *(const float4*)(gA1 + kc * 16);
        bv0 = *(const float4*)(gB0 + (size_t)kc * 16 * H_S);
        bv1 = *(const float4*)(gB1 + (size_t)kc * 16 * H_S);
        compute((kc - 1) & 1);
        store_chunk(kc & 1, av0, av1, bv0, bv1);
        __syncthreads();
    }
    compute((KTILES - 1) & 1);

    // epilogue: scores partial = sum_cols v[c]*tanh(hp + cb[c])
    float part[2][2] = {{0.0f, 0.0f}, {0.0f, 0.0f}};
#pragma unroll
    for (int mf = 0; mf < 2; mf++)
#pragma unroll
        for (int nf = 0; nf < 8; nf++) {
            const int c = col0 + nf * 8 + 2 * (lane & 3);
            const float vb0 = s_v[c], vb1 = s_v[c + 1];
            const float cb0 = s_cb[c], cb1 = s_cb[c + 1];
            part[mf][0] += vb0 * tanhf(acc[mf][nf][0] + cb0)
                         + vb1 * tanhf(acc[mf][nf][1] + cb1);
            part[mf][1] += vb0 * tanhf(acc[mf][nf][2] + cb0)
                         + vb1 * tanhf(acc[mf][nf][3] + cb1);
        }

#pragma unroll
    for (int mf = 0; mf < 2; mf++)
#pragma unroll
        for (int rh = 0; rh < 2; rh++) {
            float p = part[mf][rh];
            p += __shfl_xor_sync(0xffffffffu, p, 1);
            p += __shfl_xor_sync(0xffffffffu, p, 2);
            if ((lane & 3) == 0) {
                const int row = rowBase + row0 + mf * 16 + rh * 8 + (lane >> 2);
                atomicAdd(&g_scores[row], p);
            }
        }
}

// ---------------------------------------------------------------------------
// Launch 3: softmax over T per batch. grid 32, block 1024
// ---------------------------------------------------------------------------
__global__ void softmax_kernel() {
    __shared__ float red[32];
    const int n = blockIdx.x, tid = threadIdx.x;
    const float s0 = g_scores[n * T_S + tid];
    const float s1 = g_scores[n * T_S + 1024 + tid];

    float m = fmaxf(s0, s1);
#pragma unroll
    for (int o = 16; o > 0; o >>= 1) m = fmaxf(m, __shfl_xor_sync(~0u, m, o));
    if ((tid & 31) == 0) red[tid >> 5] = m;
    __syncthreads();
    if (tid < 32) {
        float x = red[tid];
#pragma unroll
        for (int o = 16; o > 0; o >>= 1) x = fmaxf(x, __shfl_xor_sync(~0u, x, o));
        if (tid == 0) red[0] = x;
    }
    __syncthreads();
    const float M = red[0];
    __syncthreads();

    const float e0 = __expf(s0 - M), e1 = __expf(s1 - M);
    float s = e0 + e1;
#pragma unroll
    for (int o = 16; o > 0; o >>= 1) s += __shfl_xor_sync(~0u, s, o);
    if ((tid & 31) == 0) red[tid >> 5] = s;
    __syncthreads();
    if (tid < 32) {
        float x = red[tid];
#pragma unroll
        for (int o = 16; o > 0; o >>= 1) x += __shfl_xor_sync(~0u, x, o);
        if (tid == 0) red[0] = x;
    }
    __syncthreads();
    const float inv = 1.0f / red[0];
    g_weights[n * T_S + tid] = e0 * inv;
    g_weights[n * T_S + 1024 + tid] = e1 * inv;
}

// ---------------------------------------------------------------------------
// Launch 4: context[n,h] = sum_t w[n,t] * gru[n,t,h], split over t-chunks
// grid (32, 8, 8), block 128
// ---------------------------------------------------------------------------
__global__ void context_kernel(const float* __restrict__ gru, float* __restrict__ out) {
    __shared__ float sw[256];
    const int n = blockIdx.x, hc = blockIdx.y, tc = blockIdx.z;
    const int tid = threadIdx.x;
    const int t0 = tc * 256;
    sw[tid] = g_weights[n * T_S + t0 + tid];
    sw[tid + 128] = g_weights[n * T_S + t0 + tid + 128];
    __syncthreads();

    const int h = hc * 128 + tid;
    const float* g = gru + ((size_t)n * T_S + t0) * H_S + h;
    float acc = 0.0f;
#pragma unroll 8
    for (int t = 0; t < 256; t++)
        acc = fmaf(sw[t], g[(size_t)t * H_S], acc);
    atomicAdd(&out[n * H_S + h], acc);
}

// ---------------------------------------------------------------------------
extern "C" void kernel_launch(void* const* d_in, const int* in_sizes, int n_in,
                              void* d_out, int out_size) {
    const float* gru  = (const float*)d_in[0];  // (32, 2048, 1024)
    const float* cond = (const float*)d_in[1];  // (32, 384)
    const float* Wh   = (const float*)d_in[2];  // (1024, 1024)
    const float* Wc   = (const float*)d_in[3];  // (384, 1024)
    const float* bias = (const float*)d_in[4];  // (1024,)
    const float* v    = (const float*)d_in[5];  // (1024,)
    float* out = (float*)d_out;                 // (32, 1024)

    prep_kernel<<<dim3(32, 4), 256>>>(cond, Wc, bias, out);
    gemm_scores_kernel<<<dim3(8, 512), 256>>>(gru, Wh, v);
    softmax_kernel<<<32, 1024>>>();
    context_kernel<<<dim3(32, 8, 8), 128>>>(gru, out);
}

// round 5
// speedup vs baseline: 1.3177x; 1.3177x over previous
#include <cuda_runtime.h>
#include <cstdint>
#include <math.h>

#define N_B 32
#define T_S 2048
#define H_S 1024
#define D_S 384
#define ROWS (N_B * T_S)   // 65536

// scratch (no allocations allowed)
__device__ float g_cb[N_B * H_S];       // c_proj + bias
__device__ float g_scores[ROWS];
__device__ float g_weights[ROWS];
__device__ float g_WhT[H_S * H_S];      // WhT[c][k] = Wh[k][c]

// ---------------------------------------------------------------------------
// helpers
// ---------------------------------------------------------------------------
__device__ __forceinline__ uint32_t smem_u32(const void* p) {
    uint32_t a;
    asm("{ .reg .u64 t; cvta.to.shared.u64 t, %1; cvt.u32.u64 %0, t; }" : "=r"(a) : "l"(p));
    return a;
}
__device__ __forceinline__ float tanha(float x) {
    asm("tanh.approx.f32 %0, %0;" : "+f"(x));
    return x;
}
__device__ __forceinline__ void cp_async16(uint32_t dst, const void* src) {
    asm volatile("cp.async.cg.shared.global [%0], [%1], 16;" :: "r"(dst), "l"(src) : "memory");
}
__device__ __forceinline__ void ldmx4(uint32_t r[4], uint32_t addr) {
    asm volatile("ldmatrix.sync.aligned.m8n8.x4.shared.b16 {%0,%1,%2,%3}, [%4];"
                 : "=r"(r[0]), "=r"(r[1]), "=r"(r[2]), "=r"(r[3]) : "r"(addr));
}
__device__ __forceinline__ void mma8(float c[4], const uint32_t a[4], uint32_t b0, uint32_t b1) {
    asm volatile(
        "mma.sync.aligned.m16n8k8.row.col.f32.tf32.tf32.f32 "
        "{%0,%1,%2,%3}, {%4,%5,%6,%7}, {%8,%9}, {%0,%1,%2,%3};\n"
        : "+f"(c[0]), "+f"(c[1]), "+f"(c[2]), "+f"(c[3])
        : "r"(a[0]), "r"(a[1]), "r"(a[2]), "r"(a[3]), "r"(b0), "r"(b1));
}

// ---------------------------------------------------------------------------
// Launch 1: cb[n][k] = bias[k] + cond[n]·Wc[:,k]; zero scores, out
// ---------------------------------------------------------------------------
__global__ void prep_kernel(const float* __restrict__ cond,
                            const float* __restrict__ Wc,
                            const float* __restrict__ bias,
                            float* __restrict__ out) {
    const int n = blockIdx.x;
    const int k = blockIdx.y * 256 + threadIdx.x;
    float acc = bias[k];
    const float* cp = cond + n * D_S;
#pragma unroll 4
    for (int d = 0; d < D_S; d++)
        acc = fmaf(cp[d], Wc[d * H_S + k], acc);
    g_cb[n * H_S + k] = acc;
    out[n * H_S + k] = 0.0f;
    g_scores[n * T_S + blockIdx.y * 512 + threadIdx.x] = 0.0f;
    g_scores[n * T_S + blockIdx.y * 512 + threadIdx.x + 256] = 0.0f;
}

// ---------------------------------------------------------------------------
// Launch 2: transpose Wh -> g_WhT. grid (32,32), block (32,8)
// ---------------------------------------------------------------------------
__global__ void transpose_wh(const float* __restrict__ Wh) {
    __shared__ float t[32][33];
    const int c0 = blockIdx.x * 32, k0 = blockIdx.y * 32;
    const int tx = threadIdx.x, ty = threadIdx.y;
#pragma unroll
    for (int i = 0; i < 4; i++)
        t[ty + 8 * i][tx] = Wh[(size_t)(k0 + ty + 8 * i) * H_S + c0 + tx];
    __syncthreads();
#pragma unroll
    for (int i = 0; i < 4; i++)
        g_WhT[(size_t)(c0 + ty + 8 * i) * H_S + k0 + tx] = t[tx][ty + 8 * i];
}

// ---------------------------------------------------------------------------
// Launch 3: tf32 mma.sync GEMM (128x128x1024 per CTA) + fused v·tanh epilogue
// ldmatrix fragment loads, cp.async double-buffered, rows padded to 80B.
// grid (8 col-chunks, 512 row-tiles), block 256 (8 warps, 4x2 warp grid)
// ---------------------------------------------------------------------------
#define BK 16
#define KT (H_S / BK)       // 64
#define ROWB 20             // floats per smem row (80 bytes, conflict-free LDSM)
#define STAGE_F (128 * ROWB)  // 2560 floats = 10240 B

__global__ __launch_bounds__(256, 2) void gemm_scores_mma(
    const float* __restrict__ gru, const float* __restrict__ v) {
    __shared__ float sA[2][STAGE_F];
    __shared__ float sB[2][STAGE_F];
    __shared__ float2 vcb[128];

    const int tid = threadIdx.x, wid = tid >> 5, lane = tid & 31;
    const int colBase = blockIdx.x * 128;
    const int rowBase = blockIdx.y * 128;
    const int n = rowBase >> 11;   // 128-row tiles never straddle a batch

    if (tid < 128)
        vcb[tid] = make_float2(v[colBase + tid], g_cb[n * H_S + colBase + tid]);

    const uint32_t aBase = smem_u32(sA);
    const uint32_t bBase = smem_u32(sB);

    // --- gmem -> smem mapping (2 x 16B per thread per operand per stage)
    const int lr = tid >> 2;          // row 0..63 (+64 on second)
    const int lcc = tid & 3;          // 16B chunk 0..3 within BK*4=64B
    const float* srcA0 = gru + (size_t)(rowBase + lr) * H_S + lcc * 4;
    const float* srcA1 = srcA0 + (size_t)64 * H_S;
    const float* srcB0 = g_WhT + (size_t)(colBase + lr) * H_S + lcc * 4;
    const float* srcB1 = srcB0 + (size_t)64 * H_S;
    const uint32_t dOff0 = (uint32_t)(lr * 80 + lcc * 16);
    const uint32_t dOff1 = dOff0 + 64 * 80;

    // --- warp tile: rows0 = 32*(wid&3), cols0 = 64*(wid>>2)
    const int rows0 = (wid & 3) * 32;
    const int cols0 = (wid >> 2) * 64;
    const int sel = lane >> 3, j = lane & 7;
    // per-thread ldmatrix base addresses (byte offsets within stage)
    const uint32_t aOff = (uint32_t)((rows0 + (sel & 1) * 8 + j) * 80 + (sel >> 1) * 16);
    const uint32_t bOff = (uint32_t)((cols0 + (sel >> 1) * 8 + j) * 80 + (sel & 1) * 16);

    float acc[2][8][4];
#pragma unroll
    for (int i = 0; i < 2; i++)
#pragma unroll
        for (int f = 0; f < 8; f++)
#pragma unroll
            for (int q = 0; q < 4; q++) acc[i][f][q] = 0.0f;

    auto issue = [&](int s, int kc) {
        const uint32_t sa = aBase + s * (STAGE_F * 4);
        const uint32_t sbb = bBase + s * (STAGE_F * 4);
        cp_async16(sa + dOff0, srcA0 + kc * BK);
        cp_async16(sa + dOff1, srcA1 + kc * BK);
        cp_async16(sbb + dOff0, srcB0 + kc * BK);
        cp_async16(sbb + dOff1, srcB1 + kc * BK);
        asm volatile("cp.async.commit_group;" ::: "memory");
    };

    issue(0, 0);

#pragma unroll 1
    for (int kc = 0; kc < KT; kc++) {
        if (kc + 1 < KT) {
            issue((kc + 1) & 1, kc + 1);
            asm volatile("cp.async.wait_group 1;" ::: "memory");
        } else {
            asm volatile("cp.async.wait_group 0;" ::: "memory");
        }
        __syncthreads();

        const uint32_t Ab = aBase + (kc & 1) * (STAGE_F * 4) + aOff;
        const uint32_t Bb = bBase + (kc & 1) * (STAGE_F * 4) + bOff;
#pragma unroll
        for (int ks = 0; ks < 2; ks++) {
            uint32_t af[2][4], bf[4][4];
#pragma unroll
            for (int mf = 0; mf < 2; mf++)
                ldmx4(af[mf], Ab + mf * (16 * 80) + ks * 32);
#pragma unroll
            for (int nb = 0; nb < 4; nb++)
                ldmx4(bf[nb], Bb + nb * (16 * 80) + ks * 32);
#pragma unroll
            for (int nb = 0; nb < 4; nb++) {
                mma8(acc[0][2 * nb + 0], af[0], bf[nb][0], bf[nb][1]);
                mma8(acc[1][2 * nb + 0], af[1], bf[nb][0], bf[nb][1]);
                mma8(acc[0][2 * nb + 1], af[0], bf[nb][2], bf[nb][3]);
                mma8(acc[1][2 * nb + 1], af[1], bf[nb][2], bf[nb][3]);
            }
        }
        __syncthreads();
    }

    // --- epilogue: partial score = sum_cols v[c] * tanh(hp + cb[c])
    float part[2][2] = {{0.0f, 0.0f}, {0.0f, 0.0f}};
#pragma unroll
    for (int mf = 0; mf < 2; mf++)
#pragma unroll
        for (int nf = 0; nf < 8; nf++) {
            const int c = cols0 + nf * 8 + 2 * (lane & 3);
            const float2 vc0 = vcb[c], vc1 = vcb[c + 1];
            part[mf][0] += vc0.x * tanha(acc[mf][nf][0] + vc0.y)
                         + vc1.x * tanha(acc[mf][nf][1] + vc1.y);
            part[mf][1] += vc0.x * tanha(acc[mf][nf][2] + vc0.y)
                         + vc1.x * tanha(acc[mf][nf][3] + vc1.y);
        }

#pragma unroll
    for (int mf = 0; mf < 2; mf++)
#pragma unroll
        for (int rh = 0; rh < 2; rh++) {
            float p = part[mf][rh];
            p += __shfl_xor_sync(0xffffffffu, p, 1);
            p += __shfl_xor_sync(0xffffffffu, p, 2);
            if ((lane & 3) == 0) {
                const int row = rowBase + rows0 + mf * 16 + rh * 8 + (lane >> 2);
                atomicAdd(&g_scores[row], p);
            }
        }
}

// ---------------------------------------------------------------------------
// Launch 4: softmax over T per batch. grid 32, block 1024
// ---------------------------------------------------------------------------
__global__ void softmax_kernel() {
    __shared__ float red[32];
    const int n = blockIdx.x, tid = threadIdx.x;
    const float s0 = g_scores[n * T_S + tid];
    const float s1 = g_scores[n * T_S + 1024 + tid];

    float m = fmaxf(s0, s1);
#pragma unroll
    for (int o = 16; o > 0; o >>= 1) m = fmaxf(m, __shfl_xor_sync(~0u, m, o));
    if ((tid & 31) == 0) red[tid >> 5] = m;
    __syncthreads();
    if (tid < 32) {
        float x = red[tid];
#pragma unroll
        for (int o = 16; o > 0; o >>= 1) x = fmaxf(x, __shfl_xor_sync(~0u, x, o));
        if (tid == 0) red[0] = x;
    }
    __syncthreads();
    const float M = red[0];
    __syncthreads();

    const float e0 = __expf(s0 - M), e1 = __expf(s1 - M);
    float s = e0 + e1;
#pragma unroll
    for (int o = 16; o > 0; o >>= 1) s += __shfl_xor_sync(~0u, s, o);
    if ((tid & 31) == 0) red[tid >> 5] = s;
    __syncthreads();
    if (tid < 32) {
        float x = red[tid];
#pragma unroll
        for (int o = 16; o > 0; o >>= 1) x += __shfl_xor_sync(~0u, x, o);
        if (tid == 0) red[0] = x;
    }
    __syncthreads();
    const float inv = 1.0f / red[0];
    g_weights[n * T_S + tid] = e0 * inv;
    g_weights[n * T_S + 1024 + tid] = e1 * inv;
}

// ---------------------------------------------------------------------------
// Launch 5: context[n,h] = sum_t w[n,t]*gru[n,t,h], float4. grid (32,2,8)
// ---------------------------------------------------------------------------
__global__ void context_kernel(const float* __restrict__ gru, float* __restrict__ out) {
    __shared__ float sw[256];
    const int n = blockIdx.x, hc = blockIdx.y, tc = blockIdx.z;
    const int tid = threadIdx.x;
    const int t0 = tc * 256;
    sw[tid] = g_weights[n * T_S + t0 + tid];
    sw[tid + 128] = g_weights[n * T_S + t0 + tid + 128];
    __syncthreads();

    const int h = hc * 512 + tid * 4;
    const float4* g = (const float4*)(gru + ((size_t)n * T_S + t0) * H_S + h);
    float4 acc = make_float4(0.f, 0.f, 0.f, 0.f);
#pragma unroll 4
    for (int t = 0; t < 256; t++) {
        const float4 x = g[(size_t)t * (H_S / 4)];
        const float w = sw[t];
        acc.x = fmaf(w, x.x, acc.x);
        acc.y = fmaf(w, x.y, acc.y);
        acc.z = fmaf(w, x.z, acc.z);
        acc.w = fmaf(w, x.w, acc.w);
    }
    atomicAdd(&out[n * H_S + h + 0], acc.x);
    atomicAdd(&out[n * H_S + h + 1], acc.y);
    atomicAdd(&out[n * H_S + h + 2], acc.z);
    atomicAdd(&out[n * H_S + h + 3], acc.w);
}

// ---------------------------------------------------------------------------
extern "C" void kernel_launch(void* const* d_in, const int* in_sizes, int n_in,
                              void* d_out, int out_size) {
    const float* gru  = (const float*)d_in[0];  // (32, 2048, 1024)
    const float* cond = (const float*)d_in[1];  // (32, 384)
    const float* Wh   = (const float*)d_in[2];  // (1024, 1024)
    const float* Wc   = (const float*)d_in[3];  // (384, 1024)
    const float* bias = (const float*)d_in[4];  // (1024,)
    const float* v    = (const float*)d_in[5];  // (1024,)
    float* out = (float*)d_out;                 // (32, 1024)

    prep_kernel<<<dim3(32, 4), 256>>>(cond, Wc, bias, out);
    transpose_wh<<<dim3(32, 32), dim3(32, 8)>>>(Wh);
    gemm_scores_mma<<<dim3(8, 512), 256>>>(gru, v);
    softmax_kernel<<<32, 1024>>>();
    context_kernel<<<dim3(32, 2, 8), 128>>>(gru, out);
}

// round 6
// speedup vs baseline: 1.3831x; 1.0496x over previous
#include <cuda_runtime.h>
#include <cstdint>
#include <math.h>

#define N_B 32
#define T_S 2048
#define H_S 1024
#define D_S 384
#define ROWS (N_B * T_S)   // 65536

// scratch (no allocations allowed)
__device__ float g_cb[N_B * H_S];       // c_proj + bias
__device__ float g_scores[ROWS];
__device__ float g_weights[ROWS];
__device__ float g_WhT[H_S * H_S];      // WhT[c][k] = Wh[k][c]

// ---------------------------------------------------------------------------
// helpers
// ---------------------------------------------------------------------------
__device__ __forceinline__ uint32_t smem_u32(const void* p) {
    uint32_t a;
    asm("{ .reg .u64 t; cvta.to.shared.u64 t, %1; cvt.u32.u64 %0, t; }" : "=r"(a) : "l"(p));
    return a;
}
__device__ __forceinline__ float tanha(float x) {
    asm("tanh.approx.f32 %0, %0;" : "+f"(x));
    return x;
}
__device__ __forceinline__ void cp_async16(uint32_t dst, const void* src) {
    asm volatile("cp.async.cg.shared.global [%0], [%1], 16;" :: "r"(dst), "l"(src) : "memory");
}
__device__ __forceinline__ void ldmx4(uint32_t r[4], uint32_t addr) {
    asm volatile("ldmatrix.sync.aligned.m8n8.x4.shared.b16 {%0,%1,%2,%3}, [%4];"
                 : "=r"(r[0]), "=r"(r[1]), "=r"(r[2]), "=r"(r[3]) : "r"(addr));
}
__device__ __forceinline__ void mma8(float c[4], const uint32_t a[4], uint32_t b0, uint32_t b1) {
    asm volatile(
        "mma.sync.aligned.m16n8k8.row.col.f32.tf32.tf32.f32 "
        "{%0,%1,%2,%3}, {%4,%5,%6,%7}, {%8,%9}, {%0,%1,%2,%3};\n"
        : "+f"(c[0]), "+f"(c[1]), "+f"(c[2]), "+f"(c[3])
        : "r"(a[0]), "r"(a[1]), "r"(a[2]), "r"(a[3]), "r"(b0), "r"(b1));
}

// ---------------------------------------------------------------------------
// Launch 1: cb[n][k] = bias[k] + cond[n]·Wc[:,k]; zero scores, out
// ---------------------------------------------------------------------------
__global__ void prep_kernel(const float* __restrict__ cond,
                            const float* __restrict__ Wc,
                            const float* __restrict__ bias,
                            float* __restrict__ out) {
    const int n = blockIdx.x;
    const int k = blockIdx.y * 256 + threadIdx.x;
    float acc = bias[k];
    const float* cp = cond + n * D_S;
#pragma unroll 4
    for (int d = 0; d < D_S; d++)
        acc = fmaf(cp[d], Wc[d * H_S + k], acc);
    g_cb[n * H_S + k] = acc;
    out[n * H_S + k] = 0.0f;
    g_scores[n * T_S + blockIdx.y * 512 + threadIdx.x] = 0.0f;
    g_scores[n * T_S + blockIdx.y * 512 + threadIdx.x + 256] = 0.0f;
}

// ---------------------------------------------------------------------------
// Launch 2: transpose Wh -> g_WhT. grid (32,32), block (32,8)
// ---------------------------------------------------------------------------
__global__ void transpose_wh(const float* __restrict__ Wh) {
    __shared__ float t[32][33];
    const int c0 = blockIdx.x * 32, k0 = blockIdx.y * 32;
    const int tx = threadIdx.x, ty = threadIdx.y;
#pragma unroll
    for (int i = 0; i < 4; i++)
        t[ty + 8 * i][tx] = Wh[(size_t)(k0 + ty + 8 * i) * H_S + c0 + tx];
    __syncthreads();
#pragma unroll
    for (int i = 0; i < 4; i++)
        g_WhT[(size_t)(c0 + ty + 8 * i) * H_S + k0 + tx] = t[tx][ty + 8 * i];
}

// ---------------------------------------------------------------------------
// Launch 3: tf32 mma.sync GEMM 128x256x1024 per CTA + fused v·tanh epilogue
// BK=32, 3-stage cp.async pipeline, one __syncthreads per K-iter.
// grid (4 col-chunks, 512 row-tiles), block 512 (16 warps, 4x4 warp grid)
// ---------------------------------------------------------------------------
#define BK 32
#define KT (H_S / BK)        // 32
#define RB 144               // smem row stride in bytes (128B data + 16B pad)
#define A_BYTES (128 * RB)   // 18432
#define B_BYTES (256 * RB)   // 36864
#define STG_BYTES (A_BYTES + B_BYTES)  // 55296
#define NST 3
#define VCB_OFF (NST * STG_BYTES)      // 165888
#define SMEM_TOT (VCB_OFF + 256 * 8)   // 167936

__global__ __launch_bounds__(512, 1) void gemm_scores_mma(
    const float* __restrict__ gru, const float* __restrict__ v) {
    extern __shared__ __align__(128) char smem[];
    const uint32_t sb = smem_u32(smem);
    float2* vcb = (float2*)(smem + VCB_OFF);

    const int tid = threadIdx.x, wid = tid >> 5, lane = tid & 31;
    const int colBase = blockIdx.x * 256;
    const int rowBase = blockIdx.y * 128;
    const int n = rowBase >> 11;   // 128-row tiles never straddle a batch

    if (tid < 256)
        vcb[tid] = make_float2(v[colBase + tid], g_cb[n * H_S + colBase + tid]);

    // --- gmem -> smem mapping: per stage, A = 2 chunks, B = 4 chunks of 16B
    const int lr = tid >> 3;          // row 0..63
    const int lcc = tid & 7;          // 16B chunk within 128B row
    const float* srcA = gru + (size_t)(rowBase + lr) * H_S + lcc * 4;
    const float* srcB = g_WhT + (size_t)(colBase + lr) * H_S + lcc * 4;
    const uint32_t dA = (uint32_t)(lr * RB + lcc * 16);
    const uint32_t dB = dA;

    // --- warp tile: rows 32*(wid&3), cols 64*(wid>>2)
    const int rows0 = (wid & 3) * 32;
    const int cols0 = (wid >> 2) * 64;
    const int sel = lane >> 3, j = lane & 7;
    const uint32_t aOff = (uint32_t)((rows0 + (sel & 1) * 8 + j) * RB + (sel >> 1) * 16);
    const uint32_t bOff = (uint32_t)((cols0 + (sel >> 1) * 8 + j) * RB + (sel & 1) * 16);

    float acc[2][8][4];
#pragma unroll
    for (int i = 0; i < 2; i++)
#pragma unroll
        for (int f = 0; f < 8; f++)
#pragma unroll
            for (int q = 0; q < 4; q++) acc[i][f][q] = 0.0f;

    auto issue = [&](int s, int kc) {
        const uint32_t sa = sb + s * STG_BYTES;
        const uint32_t sbb = sa + A_BYTES;
        const float* pa = srcA + kc * BK;
        const float* pb = srcB + kc * BK;
        cp_async16(sa + dA, pa);
        cp_async16(sa + dA + 64 * RB, pa + (size_t)64 * H_S);
#pragma unroll
        for (int i = 0; i < 4; i++)
            cp_async16(sbb + dB + i * (64 * RB), pb + (size_t)(64 * i) * H_S);
        asm volatile("cp.async.commit_group;" ::: "memory");
    };

    issue(0, 0);
    issue(1, 1);

#pragma unroll 1
    for (int kc = 0; kc < KT; kc++) {
        if (kc + 1 < KT)
            asm volatile("cp.async.wait_group 1;" ::: "memory");
        else
            asm volatile("cp.async.wait_group 0;" ::: "memory");
        __syncthreads();
        if (kc + 2 < KT) issue((kc + 2) % NST, kc + 2);

        const uint32_t base = sb + (kc % NST) * STG_BYTES;
        const uint32_t Ab = base + aOff;
        const uint32_t Bb = base + A_BYTES + bOff;
#pragma unroll
        for (int ks = 0; ks < 4; ks++) {
            uint32_t af[2][4], bf[4][4];
#pragma unroll
            for (int mf = 0; mf < 2; mf++)
                ldmx4(af[mf], Ab + mf * (16 * RB) + ks * 32);
#pragma unroll
            for (int nb = 0; nb < 4; nb++)
                ldmx4(bf[nb], Bb + nb * (16 * RB) + ks * 32);
#pragma unroll
            for (int nb = 0; nb < 4; nb++) {
                mma8(acc[0][2 * nb + 0], af[0], bf[nb][0], bf[nb][1]);
                mma8(acc[1][2 * nb + 0], af[1], bf[nb][0], bf[nb][1]);
                mma8(acc[0][2 * nb + 1], af[0], bf[nb][2], bf[nb][3]);
                mma8(acc[1][2 * nb + 1], af[1], bf[nb][2], bf[nb][3]);
            }
        }
    }

    // --- epilogue: partial score = sum_cols v[c] * tanh(hp + cb[c])
    float part[2][2] = {{0.0f, 0.0f}, {0.0f, 0.0f}};
#pragma unroll
    for (int mf = 0; mf < 2; mf++)
#pragma unroll
        for (int nf = 0; nf < 8; nf++) {
            const int c = cols0 + nf * 8 + 2 * (lane & 3);
            const float2 vc0 = vcb[c], vc1 = vcb[c + 1];
            part[mf][0] += vc0.x * tanha(acc[mf][nf][0] + vc0.y)
                         + vc1.x * tanha(acc[mf][nf][1] + vc1.y);
            part[mf][1] += vc0.x * tanha(acc[mf][nf][2] + vc0.y)
                         + vc1.x * tanha(acc[mf][nf][3] + vc1.y);
        }

#pragma unroll
    for (int mf = 0; mf < 2; mf++)
#pragma unroll
        for (int rh = 0; rh < 2; rh++) {
            float p = part[mf][rh];
            p += __shfl_xor_sync(0xffffffffu, p, 1);
            p += __shfl_xor_sync(0xffffffffu, p, 2);
            if ((lane & 3) == 0) {
                const int row = rowBase + rows0 + mf * 16 + rh * 8 + (lane >> 2);
                atomicAdd(&g_scores[row], p);
            }
        }
}

// ---------------------------------------------------------------------------
// Launch 4: softmax over T per batch. grid 32, block 1024
// ---------------------------------------------------------------------------
__global__ void softmax_kernel() {
    __shared__ float red[32];
    const int n = blockIdx.x, tid = threadIdx.x;
    const float s0 = g_scores[n * T_S + tid];
    const float s1 = g_scores[n * T_S + 1024 + tid];

    float m = fmaxf(s0, s1);
#pragma unroll
    for (int o = 16; o > 0; o >>= 1) m = fmaxf(m, __shfl_xor_sync(~0u, m, o));
    if ((tid & 31) == 0) red[tid >> 5] = m;
    __syncthreads();
    if (tid < 32) {
        float x = red[tid];
#pragma unroll
        for (int o = 16; o > 0; o >>= 1) x = fmaxf(x, __shfl_xor_sync(~0u, x, o));
        if (tid == 0) red[0] = x;
    }
    __syncthreads();
    const float M = red[0];
    __syncthreads();

    const float e0 = __expf(s0 - M), e1 = __expf(s1 - M);
    float s = e0 + e1;
#pragma unroll
    for (int o = 16; o > 0; o >>= 1) s += __shfl_xor_sync(~0u, s, o);
    if ((tid & 31) == 0) red[tid >> 5] = s;
    __syncthreads();
    if (tid < 32) {
        float x = red[tid];
#pragma unroll
        for (int o = 16; o > 0; o >>= 1) x += __shfl_xor_sync(~0u, x, o);
        if (tid == 0) red[0] = x;
    }
    __syncthreads();
    const float inv = 1.0f / red[0];
    g_weights[n * T_S + tid] = e0 * inv;
    g_weights[n * T_S + 1024 + tid] = e1 * inv;
}

// ---------------------------------------------------------------------------
// Launch 5: context[n,h] = sum_t w[n,t]*gru[n,t,h], float4. grid (32,2,8)
// ---------------------------------------------------------------------------
__global__ void context_kernel(const float* __restrict__ gru, float* __restrict__ out) {
    __shared__ float sw[256];
    const int n = blockIdx.x, hc = blockIdx.y, tc = blockIdx.z;
    const int tid = threadIdx.x;
    const int t0 = tc * 256;
    sw[tid] = g_weights[n * T_S + t0 + tid];
    sw[tid + 128] = g_weights[n * T_S + t0 + tid + 128];
    __syncthreads();

    const int h = hc * 512 + tid * 4;
    const float4* g = (const float4*)(gru + ((size_t)n * T_S + t0) * H_S + h);
    float4 acc = make_float4(0.f, 0.f, 0.f, 0.f);
#pragma unroll 4
    for (int t = 0; t < 256; t++) {
        const float4 x = g[(size_t)t * (H_S / 4)];
        const float w = sw[t];
        acc.x = fmaf(w, x.x, acc.x);
        acc.y = fmaf(w, x.y, acc.y);
        acc.z = fmaf(w, x.z, acc.z);
        acc.w = fmaf(w, x.w, acc.w);
    }
    atomicAdd(&out[n * H_S + h + 0], acc.x);
    atomicAdd(&out[n * H_S + h + 1], acc.y);
    atomicAdd(&out[n * H_S + h + 2], acc.z);
    atomicAdd(&out[n * H_S + h + 3], acc.w);
}

// ---------------------------------------------------------------------------
extern "C" void kernel_launch(void* const* d_in, const int* in_sizes, int n_in,
                              void* d_out, int out_size) {
    const float* gru  = (const float*)d_in[0];  // (32, 2048, 1024)
    const float* cond = (const float*)d_in[1];  // (32, 384)
    const float* Wh   = (const float*)d_in[2];  // (1024, 1024)
    const float* Wc   = (const float*)d_in[3];  // (384, 1024)
    const float* bias = (const float*)d_in[4];  // (1024,)
    const float* v    = (const float*)d_in[5];  // (1024,)
    float* out = (float*)d_out;                 // (32, 1024)

    static bool attr_done = false;
    if (!attr_done) {
        cudaFuncSetAttribute(gemm_scores_mma,
                             cudaFuncAttributeMaxDynamicSharedMemorySize, SMEM_TOT);
        attr_done = true;
    }

    prep_kernel<<<dim3(32, 4), 256>>>(cond, Wc, bias, out);
    transpose_wh<<<dim3(32, 32), dim3(32, 8)>>>(Wh);
    gemm_scores_mma<<<dim3(4, 512), 512, SMEM_TOT>>>(gru, v);
    softmax_kernel<<<32, 1024>>>();
    context_kernel<<<dim3(32, 2, 8), 128>>>(gru, out);
}

// round 8
// speedup vs baseline: 2.1790x; 1.5754x over previous
#include <cuda_runtime.h>
#include <cuda_fp16.h>
#include <cstdint>
#include <math.h>

#define N_B 32
#define T_S 2048
#define H_S 1024
#define D_S 384
#define ROWS (N_B * T_S)   // 65536

// scratch (no allocations allowed)
__device__ float g_cb[N_B * H_S];        // c_proj + bias
__device__ float g_scores[ROWS];
__device__ float g_weights[ROWS];
__device__ __half g_WhTH[H_S * H_S];     // WhT[c][k] = Wh[k][c], fp16
__device__ __half g_gruH[(size_t)ROWS * H_S];  // gru in fp16 (134 MB)

// ---------------------------------------------------------------------------
// helpers
// ---------------------------------------------------------------------------
__device__ __forceinline__ uint32_t smem_u32(const void* p) {
    uint32_t a;
    asm("{ .reg .u64 t; cvta.to.shared.u64 t, %1; cvt.u32.u64 %0, t; }" : "=r"(a) : "l"(p));
    return a;
}
__device__ __forceinline__ float tanha(float x) {
    asm("tanh.approx.f32 %0, %0;" : "+f"(x));
    return x;
}
__device__ __forceinline__ void cp_async16(uint32_t dst, const void* src) {
    asm volatile("cp.async.cg.shared.global [%0], [%1], 16;" :: "r"(dst), "l"(src) : "memory");
}
__device__ __forceinline__ void ldmx4(uint32_t r[4], uint32_t addr) {
    asm volatile("ldmatrix.sync.aligned.m8n8.x4.shared.b16 {%0,%1,%2,%3}, [%4];"
                 : "=r"(r[0]), "=r"(r[1]), "=r"(r[2]), "=r"(r[3]) : "r"(addr));
}
__device__ __forceinline__ void mma16(float c[4], const uint32_t a[4], uint32_t b0, uint32_t b1) {
    asm volatile(
        "mma.sync.aligned.m16n8k16.row.col.f32.f16.f16.f32 "
        "{%0,%1,%2,%3}, {%4,%5,%6,%7}, {%8,%9}, {%0,%1,%2,%3};\n"
        : "+f"(c[0]), "+f"(c[1]), "+f"(c[2]), "+f"(c[3])
        : "r"(a[0]), "r"(a[1]), "r"(a[2]), "r"(a[3]), "r"(b0), "r"(b1));
}

// ---------------------------------------------------------------------------
// Launch 0: convert gru fp32 -> fp16. 8 floats per thread. grid 32768 x 256
// ---------------------------------------------------------------------------
__global__ void convert_gru_kernel(const float* __restrict__ g) {
    const size_t i = ((size_t)blockIdx.x * 256 + threadIdx.x) * 8;
    const float4 x0 = *(const float4*)(g + i);
    const float4 x1 = *(const float4*)(g + i + 4);
    __half2 h[4];
    h[0] = __floats2half2_rn(x0.x, x0.y);
    h[1] = __floats2half2_rn(x0.z, x0.w);
    h[2] = __floats2half2_rn(x1.x, x1.y);
    h[3] = __floats2half2_rn(x1.z, x1.w);
    *(uint4*)(g_gruH + i) = *(uint4*)h;
}

// ---------------------------------------------------------------------------
// Launch 1: cb[n][k] = bias[k] + cond[n]·Wc[:,k]; zero scores, out
// ---------------------------------------------------------------------------
__global__ void prep_kernel(const float* __restrict__ cond,
                            const float* __restrict__ Wc,
                            const float* __restrict__ bias,
                            float* __restrict__ out) {
    const int n = blockIdx.x;
    const int k = blockIdx.y * 256 + threadIdx.x;
    float acc = bias[k];
    const float* cp = cond + n * D_S;
#pragma unroll 4
    for (int d = 0; d < D_S; d++)
        acc = fmaf(cp[d], Wc[d * H_S + k], acc);
    g_cb[n * H_S + k] = acc;
    out[n * H_S + k] = 0.0f;
    g_scores[n * T_S + blockIdx.y * 512 + threadIdx.x] = 0.0f;
    g_scores[n * T_S + blockIdx.y * 512 + threadIdx.x + 256] = 0.0f;
}

// ---------------------------------------------------------------------------
// Launch 2: transpose Wh -> g_WhTH (fp16). grid (32,32), block (32,8)
// ---------------------------------------------------------------------------
__global__ void transpose_wh(const float* __restrict__ Wh) {
    __shared__ float t[32][33];
    const int c0 = blockIdx.x * 32, k0 = blockIdx.y * 32;
    const int tx = threadIdx.x, ty = threadIdx.y;
#pragma unroll
    for (int i = 0; i < 4; i++)
        t[ty + 8 * i][tx] = Wh[(size_t)(k0 + ty + 8 * i) * H_S + c0 + tx];
    __syncthreads();
#pragma unroll
    for (int i = 0; i < 4; i++)
        g_WhTH[(size_t)(c0 + ty + 8 * i) * H_S + k0 + tx] = __float2half_rn(t[tx][ty + 8 * i]);
}

// ---------------------------------------------------------------------------
// Launch 3: fp16 m16n8k16 GEMM 128x256x1024 per CTA + fused v·tanh epilogue
// BK=64 halves (128B/row), 3-stage cp.async, one __syncthreads per K-iter.
// grid (4 col-chunks, 512 row-tiles), block 512 (16 warps, 4x4 warp grid)
// ---------------------------------------------------------------------------
#define BK 64
#define KT (H_S / BK)        // 16
#define RB 144               // smem row stride bytes (128B data + 16B pad)
#define A_BYTES (128 * RB)   // 18432
#define B_BYTES (256 * RB)   // 36864
#define STG_BYTES (A_BYTES + B_BYTES)  // 55296
#define NST 3
#define VCB_OFF (NST * STG_BYTES)      // 165888
#define SMEM_TOT (VCB_OFF + 256 * 8)   // 167936

__global__ __launch_bounds__(512, 1) void gemm_scores_mma(
    const float* __restrict__ v) {
    extern __shared__ __align__(128) char smem[];
    const uint32_t sb = smem_u32(smem);
    float2* vcb = (float2*)(smem + VCB_OFF);

    const int tid = threadIdx.x, wid = tid >> 5, lane = tid & 31;
    const int colBase = blockIdx.x * 256;
    const int rowBase = blockIdx.y * 128;
    const int n = rowBase >> 11;   // 128-row tiles never straddle a batch

    if (tid < 256)
        vcb[tid] = make_float2(v[colBase + tid], g_cb[n * H_S + colBase + tid]);

    // --- gmem -> smem: per stage, A = 2 x 16B, B = 4 x 16B per thread
    const int lr = tid >> 3;          // row 0..63
    const int lcc = tid & 7;          // 16B chunk within 128B row
    const __half* srcA = g_gruH + (size_t)(rowBase + lr) * H_S + lcc * 8;
    const __half* srcB = g_WhTH + (size_t)(colBase + lr) * H_S + lcc * 8;
    const uint32_t dA = (uint32_t)(lr * RB + lcc * 16);

    // --- warp tile: rows 32*(wid&3), cols 64*(wid>>2)
    const int rows0 = (wid & 3) * 32;
    const int cols0 = (wid >> 2) * 64;
    const int sel = lane >> 3, j = lane & 7;
    const uint32_t aOff = (uint32_t)((rows0 + (sel & 1) * 8 + j) * RB + (sel >> 1) * 16);
    const uint32_t bOff = (uint32_t)((cols0 + (sel >> 1) * 8 + j) * RB + (sel & 1) * 16);

    float acc[2][8][4];
#pragma unroll
    for (int i = 0; i < 2; i++)
#pragma unroll
        for (int f = 0; f < 8; f++)
#pragma unroll
            for (int q = 0; q < 4; q++) acc[i][f][q] = 0.0f;

    auto issue = [&](int s, int kc) {
        const uint32_t sa = sb + s * STG_BYTES;
        const uint32_t sbb = sa + A_BYTES;
        const __half* pa = srcA + kc * BK;
        const __half* pb = srcB + kc * BK;
        cp_async16(sa + dA, pa);
        cp_async16(sa + dA + 64 * RB, pa + (size_t)64 * H_S);
#pragma unroll
        for (int i = 0; i < 4; i++)
            cp_async16(sbb + dA + i * (64 * RB), pb + (size_t)(64 * i) * H_S);
        asm volatile("cp.async.commit_group;" ::: "memory");
    };

    issue(0, 0);
    issue(1, 1);

#pragma unroll 1
    for (int kc = 0; kc < KT; kc++) {
        if (kc + 1 < KT)
            asm volatile("cp.async.wait_group 1;" ::: "memory");
        else
            asm volatile("cp.async.wait_group 0;" ::: "memory");
        __syncthreads();
        if (kc + 2 < KT) issue((kc + 2) % NST, kc + 2);

        const uint32_t base = sb + (kc % NST) * STG_BYTES;
        const uint32_t Ab = base + aOff;
        const uint32_t Bb = base + A_BYTES + bOff;
#pragma unroll
        for (int ks = 0; ks < 4; ks++) {   // 4 k-steps of 16 halves (32B each)
            uint32_t af[2][4], bf[4][4];
#pragma unroll
            for (int mf = 0; mf < 2; mf++)
                ldmx4(af[mf], Ab + mf * (16 * RB) + ks * 32);
#pragma unroll
            for (int nb = 0; nb < 4; nb++)
                ldmx4(bf[nb], Bb + nb * (16 * RB) + ks * 32);
#pragma unroll
            for (int nb = 0; nb < 4; nb++) {
                mma16(acc[0][2 * nb + 0], af[0], bf[nb][0], bf[nb][1]);
                mma16(acc[1][2 * nb + 0], af[1], bf[nb][0], bf[nb][1]);
                mma16(acc[0][2 * nb + 1], af[0], bf[nb][2], bf[nb][3]);
                mma16(acc[1][2 * nb + 1], af[1], bf[nb][2], bf[nb][3]);
            }
        }
    }

    // --- epilogue: partial score = sum_cols v[c] * tanh(hp + cb[c])
    float part[2][2] = {{0.0f, 0.0f}, {0.0f, 0.0f}};
#pragma unroll
    for (int mf = 0; mf < 2; mf++)
#pragma unroll
        for (int nf = 0; nf < 8; nf++) {
            const int c = cols0 + nf * 8 + 2 * (lane & 3);
            const float2 vc0 = vcb[c], vc1 = vcb[c + 1];
            part[mf][0] += vc0.x * tanha(acc[mf][nf][0] + vc0.y)
                         + vc1.x * tanha(acc[mf][nf][1] + vc1.y);
            part[mf][1] += vc0.x * tanha(acc[mf][nf][2] + vc0.y)
                         + vc1.x * tanha(acc[mf][nf][3] + vc1.y);
        }

#pragma unroll
    for (int mf = 0; mf < 2; mf++)
#pragma unroll
        for (int rh = 0; rh < 2; rh++) {
            float p = part[mf][rh];
            p += __shfl_xor_sync(0xffffffffu, p, 1);
            p += __shfl_xor_sync(0xffffffffu, p, 2);
            if ((lane & 3) == 0) {
                const int row = rowBase + rows0 + mf * 16 + rh * 8 + (lane >> 2);
                atomicAdd(&g_scores[row], p);
            }
        }
}

// ---------------------------------------------------------------------------
// Launch 4: softmax over T per batch. grid 32, block 1024
// ---------------------------------------------------------------------------
__global__ void softmax_kernel() {
    __shared__ float red[32];
    const int n = blockIdx.x, tid = threadIdx.x;
    const float s0 = g_scores[n * T_S + tid];
    const float s1 = g_scores[n * T_S + 1024 + tid];

    float m = fmaxf(s0, s1);
#pragma unroll
    for (int o = 16; o > 0; o >>= 1) m = fmaxf(m, __shfl_xor_sync(~0u, m, o));
    if ((tid & 31) == 0) red[tid >> 5] = m;
    __syncthreads();
    if (tid < 32) {
        float x = red[tid];
#pragma unroll
        for (int o = 16; o > 0; o >>= 1) x = fmaxf(x, __shfl_xor_sync(~0u, x, o));
        if (tid == 0) red[0] = x;
    }
    __syncthreads();
    const float M = red[0];
    __syncthreads();

    const float e0 = __expf(s0 - M), e1 = __expf(s1 - M);
    float s = e0 + e1;
#pragma unroll
    for (int o = 16; o > 0; o >>= 1) s += __shfl_xor_sync(~0u, s, o);
    if ((tid & 31) == 0) red[tid >> 5] = s;
    __syncthreads();
    if (tid < 32) {
        float x = red[tid];
#pragma unroll
        for (int o = 16; o > 0; o >>= 1) x += __shfl_xor_sync(~0u, x, o);
        if (tid == 0) red[0] = x;
    }
    __syncthreads();
    const float inv = 1.0f / red[0];
    g_weights[n * T_S + tid] = e0 * inv;
    g_weights[n * T_S + 1024 + tid] = e1 * inv;
}

// ---------------------------------------------------------------------------
// Launch 5: context[n,h] = sum_t w[n,t]*gru[n,t,h], float4. grid (32,2,8)
// ---------------------------------------------------------------------------
__global__ void context_kernel(const float* __restrict__ gru, float* __restrict__ out) {
    __shared__ float sw[256];
    const int n = blockIdx.x, hc = blockIdx.y, tc = blockIdx.z;
    const int tid = threadIdx.x;
    const int t0 = tc * 256;
    sw[tid] = g_weights[n * T_S + t0 + tid];
    sw[tid + 128] = g_weights[n * T_S + t0 + tid + 128];
    __syncthreads();

    const int h = hc * 512 + tid * 4;
    const float4* g = (const float4*)(gru + ((size_t)n * T_S + t0) * H_S + h);
    float4 acc = make_float4(0.f, 0.f, 0.f, 0.f);
#pragma unroll 4
    for (int t = 0; t < 256; t++) {
        const float4 x = g[(size_t)t * (H_S / 4)];
        const float w = sw[t];
        acc.x = fmaf(w, x.x, acc.x);
        acc.y = fmaf(w, x.y, acc.y);
        acc.z = fmaf(w, x.z, acc.z);
        acc.w = fmaf(w, x.w, acc.w);
    }
    atomicAdd(&out[n * H_S + h + 0], acc.x);
    atomicAdd(&out[n * H_S + h + 1], acc.y);
    atomicAdd(&out[n * H_S + h + 2], acc.z);
    atomicAdd(&out[n * H_S + h + 3], acc.w);
}

// ---------------------------------------------------------------------------
extern "C" void kernel_launch(void* const* d_in, const int* in_sizes, int n_in,
                              void* d_out, int out_size) {
    const float* gru  = (const float*)d_in[0];  // (32, 2048, 1024)
    const float* cond = (const float*)d_in[1];  // (32, 384)
    const float* Wh   = (const float*)d_in[2];  // (1024, 1024)
    const float* Wc   = (const float*)d_in[3];  // (384, 1024)
    const float* bias = (const float*)d_in[4];  // (1024,)
    const float* v    = (const float*)d_in[5];  // (1024,)
    float* out = (float*)d_out;                 // (32, 1024)

    static bool attr_done = false;
    if (!attr_done) {
        cudaFuncSetAttribute(gemm_scores_mma,
                             cudaFuncAttributeMaxDynamicSharedMemorySize, SMEM_TOT);
        attr_done = true;
    }

    convert_gru_kernel<<<32768, 256>>>(gru);
    prep_kernel<<<dim3(32, 4), 256>>>(cond, Wc, bias, out);
    transpose_wh<<<dim3(32, 32), dim3(32, 8)>>>(Wh);
    gemm_scores_mma<<<dim3(4, 512), 512, SMEM_TOT>>>(v);
    softmax_kernel<<<32, 1024>>>();
    context_kernel<<<dim3(32, 2, 8), 128>>>(gru, out);
}

// round 10
// speedup vs baseline: 2.3392x; 1.0735x over previous
#include <cuda_runtime.h>
#include <cuda_fp16.h>
#include <cstdint>
#include <math.h>

#define N_B 32
#define T_S 2048
#define H_S 1024
#define D_S 384
#define ROWS (N_B * T_S)   // 65536

// scratch (no allocations allowed)
__device__ float g_cb[N_B * H_S];        // c_proj + bias
__device__ float g_scores[ROWS];
__device__ float g_weights[ROWS];
__device__ __half g_WhTH[H_S * H_S];     // WhT[c][k] = Wh[k][c], fp16
__device__ __half g_gruH[(size_t)ROWS * H_S];  // gru in fp16 (134 MB)

// ---------------------------------------------------------------------------
// helpers
// ---------------------------------------------------------------------------
__device__ __forceinline__ uint32_t smem_u32(const void* p) {
    uint32_t a;
    asm("{ .reg .u64 t; cvta.to.shared.u64 t, %1; cvt.u32.u64 %0, t; }" : "=r"(a) : "l"(p));
    return a;
}
__device__ __forceinline__ float tanha(float x) {
    asm("tanh.approx.f32 %0, %0;" : "+f"(x));
    return x;
}
__device__ __forceinline__ void cp_async16(uint32_t dst, const void* src) {
    asm volatile("cp.async.cg.shared.global [%0], [%1], 16;" :: "r"(dst), "l"(src) : "memory");
}
__device__ __forceinline__ void ldmx4(uint32_t r[4], uint32_t addr) {
    asm volatile("ldmatrix.sync.aligned.m8n8.x4.shared.b16 {%0,%1,%2,%3}, [%4];"
                 : "=r"(r[0]), "=r"(r[1]), "=r"(r[2]), "=r"(r[3]) : "r"(addr));
}
__device__ __forceinline__ void mma16(float c[4], const uint32_t a[4], uint32_t b0, uint32_t b1) {
    asm volatile(
        "mma.sync.aligned.m16n8k16.row.col.f32.f16.f16.f32 "
        "{%0,%1,%2,%3}, {%4,%5,%6,%7}, {%8,%9}, {%0,%1,%2,%3};\n"
        : "+f"(c[0]), "+f"(c[1]), "+f"(c[2]), "+f"(c[3])
        : "r"(a[0]), "r"(a[1]), "r"(a[2]), "r"(a[3]), "r"(b0), "r"(b1));
}

// ---------------------------------------------------------------------------
// Launch 0: convert gru fp32 -> fp16. 8 floats per thread. grid 32768 x 256
// ---------------------------------------------------------------------------
__global__ void convert_gru_kernel(const float* __restrict__ g) {
    const size_t i = ((size_t)blockIdx.x * 256 + threadIdx.x) * 8;
    const float4 x0 = *(const float4*)(g + i);
    const float4 x1 = *(const float4*)(g + i + 4);
    __half2 h[4];
    h[0] = __floats2half2_rn(x0.x, x0.y);
    h[1] = __floats2half2_rn(x0.z, x0.w);
    h[2] = __floats2half2_rn(x1.x, x1.y);
    h[3] = __floats2half2_rn(x1.z, x1.w);
    *(uint4*)(g_gruH + i) = *(uint4*)h;
}

// ---------------------------------------------------------------------------
// Launch 1: cb[n][k] = bias[k] + cond[n]·Wc[:,k]; zero scores, out
// ---------------------------------------------------------------------------
__global__ void prep_kernel(const float* __restrict__ cond,
                            const float* __restrict__ Wc,
                            const float* __restrict__ bias,
                            float* __restrict__ out) {
    const int n = blockIdx.x;
    const int k = blockIdx.y * 256 + threadIdx.x;
    float acc = bias[k];
    const float* cp = cond + n * D_S;
#pragma unroll 4
    for (int d = 0; d < D_S; d++)
        acc = fmaf(cp[d], Wc[d * H_S + k], acc);
    g_cb[n * H_S + k] = acc;
    out[n * H_S + k] = 0.0f;
    g_scores[n * T_S + blockIdx.y * 512 + threadIdx.x] = 0.0f;
    g_scores[n * T_S + blockIdx.y * 512 + threadIdx.x + 256] = 0.0f;
}

// ---------------------------------------------------------------------------
// Launch 2: transpose Wh -> g_WhTH (fp16). grid (32,32), block (32,8)
// ---------------------------------------------------------------------------
__global__ void transpose_wh(const float* __restrict__ Wh) {
    __shared__ float t[32][33];
    const int c0 = blockIdx.x * 32, k0 = blockIdx.y * 32;
    const int tx = threadIdx.x, ty = threadIdx.y;
#pragma unroll
    for (int i = 0; i < 4; i++)
        t[ty + 8 * i][tx] = Wh[(size_t)(k0 + ty + 8 * i) * H_S + c0 + tx];
    __syncthreads();
#pragma unroll
    for (int i = 0; i < 4; i++)
        g_WhTH[(size_t)(c0 + ty + 8 * i) * H_S + k0 + tx] = __float2half_rn(t[tx][ty + 8 * i]);
}

// ---------------------------------------------------------------------------
// Launch 3: fp16 m16n8k16 GEMM 128x128x1024 per CTA + fused v·tanh epilogue
// BK=64, 3-stage cp.async, 2 CTAs per SM (256 thr, 109KB smem each).
// grid (8 col-chunks, 512 row-tiles), block 256 (8 warps, 4x2 warp grid)
// ---------------------------------------------------------------------------
#define BK 64
#define KT (H_S / BK)        // 16
#define RB 144               // smem row stride bytes (128B data + 16B pad)
#define A_BYTES (128 * RB)   // 18432
#define B_BYTES (128 * RB)   // 18432
#define STG_BYTES (A_BYTES + B_BYTES)  // 36864
#define NST 3
#define VCB_OFF (NST * STG_BYTES)      // 110592
#define SMEM_TOT (VCB_OFF + 128 * 8)   // 111616

__global__ __launch_bounds__(256, 2) void gemm_scores_mma(
    const float* __restrict__ v) {
    extern __shared__ __align__(128) char smem[];
    const uint32_t sb = smem_u32(smem);
    float2* vcb = (float2*)(smem + VCB_OFF);

    const int tid = threadIdx.x, wid = tid >> 5, lane = tid & 31;
    const int colBase = blockIdx.x * 128;
    const int rowBase = blockIdx.y * 128;
    const int n = rowBase >> 11;   // 128-row tiles never straddle a batch

    if (tid < 128)
        vcb[tid] = make_float2(v[colBase + tid], g_cb[n * H_S + colBase + tid]);

    // --- gmem -> smem: per stage, A = 4 x 16B, B = 4 x 16B per thread
    const int lr = tid >> 3;          // row 0..31 (+32i)
    const int lcc = tid & 7;          // 16B chunk within 128B row
    const __half* srcA = g_gruH + (size_t)(rowBase + lr) * H_S + lcc * 8;
    const __half* srcB = g_WhTH + (size_t)(colBase + lr) * H_S + lcc * 8;
    const uint32_t dA = (uint32_t)(lr * RB + lcc * 16);

    // --- warp tile: rows 32*(wid&3), cols 64*(wid>>2)
    const int rows0 = (wid & 3) * 32;
    const int cols0 = (wid >> 2) * 64;
    const int sel = lane >> 3, j = lane & 7;
    const uint32_t aOff = (uint32_t)((rows0 + (sel & 1) * 8 + j) * RB + (sel >> 1) * 16);
    const uint32_t bOff = (uint32_t)((cols0 + (sel >> 1) * 8 + j) * RB + (sel & 1) * 16);

    float acc[2][8][4];
#pragma unroll
    for (int i = 0; i < 2; i++)
#pragma unroll
        for (int f = 0; f < 8; f++)
#pragma unroll
            for (int q = 0; q < 4; q++) acc[i][f][q] = 0.0f;

    auto issue = [&](int s, int kc) {
        const uint32_t sa = sb + s * STG_BYTES;
        const uint32_t sbb = sa + A_BYTES;
        const __half* pa = srcA + kc * BK;
        const __half* pb = srcB + kc * BK;
#pragma unroll
        for (int i = 0; i < 4; i++)
            cp_async16(sa + dA + i * (32 * RB), pa + (size_t)(32 * i) * H_S);
#pragma unroll
        for (int i = 0; i < 4; i++)
            cp_async16(sbb + dA + i * (32 * RB), pb + (size_t)(32 * i) * H_S);
        asm volatile("cp.async.commit_group;" ::: "memory");
    };

    issue(0, 0);
    issue(1, 1);

#pragma unroll 1
    for (int kc = 0; kc < KT; kc++) {
        if (kc + 1 < KT)
            asm volatile("cp.async.wait_group 1;" ::: "memory");
        else
            asm volatile("cp.async.wait_group 0;" ::: "memory");
        __syncthreads();
        if (kc + 2 < KT) issue((kc + 2) % NST, kc + 2);

        const uint32_t base = sb + (kc % NST) * STG_BYTES;
        const uint32_t Ab = base + aOff;
        const uint32_t Bb = base + A_BYTES + bOff;
#pragma unroll
        for (int ks = 0; ks < 4; ks++) {   // 4 k-steps of 16 halves (32B each)
            uint32_t af[2][4], bf[4][4];
#pragma unroll
            for (int mf = 0; mf < 2; mf++)
                ldmx4(af[mf], Ab + mf * (16 * RB) + ks * 32);
#pragma unroll
            for (int nb = 0; nb < 4; nb++)
                ldmx4(bf[nb], Bb + nb * (16 * RB) + ks * 32);
#pragma unroll
            for (int nb = 0; nb < 4; nb++) {
                mma16(acc[0][2 * nb + 0], af[0], bf[nb][0], bf[nb][1]);
                mma16(acc[1][2 * nb + 0], af[1], bf[nb][0], bf[nb][1]);
                mma16(acc[0][2 * nb + 1], af[0], bf[nb][2], bf[nb][3]);
                mma16(acc[1][2 * nb + 1], af[1], bf[nb][2], bf[nb][3]);
            }
        }
    }

    // --- epilogue: partial score = sum_cols v[c] * tanh(hp + cb[c])
    float part[2][2] = {{0.0f, 0.0f}, {0.0f, 0.0f}};
#pragma unroll
    for (int mf = 0; mf < 2; mf++)
#pragma unroll
        for (int nf = 0; nf < 8; nf++) {
            const int c = cols0 + nf * 8 + 2 * (lane & 3);
            const float2 vc0 = vcb[c], vc1 = vcb[c + 1];
            part[mf][0] += vc0.x * tanha(acc[mf][nf][0] + vc0.y)
                         + vc1.x * tanha(acc[mf][nf][1] + vc1.y);
            part[mf][1] += vc0.x * tanha(acc[mf][nf][2] + vc0.y)
                         + vc1.x * tanha(acc[mf][nf][3] + vc1.y);
        }

#pragma unroll
    for (int mf = 0; mf < 2; mf++)
#pragma unroll
        for (int rh = 0; rh < 2; rh++) {
            float p = part[mf][rh];
            p += __shfl_xor_sync(0xffffffffu, p, 1);
            p += __shfl_xor_sync(0xffffffffu, p, 2);
            if ((lane & 3) == 0) {
                const int row = rowBase + rows0 + mf * 16 + rh * 8 + (lane >> 2);
                atomicAdd(&g_scores[row], p);
            }
        }
}

// ---------------------------------------------------------------------------
// Launch 4: softmax over T per batch. grid 32, block 1024
// ---------------------------------------------------------------------------
__global__ void softmax_kernel() {
    __shared__ float red[32];
    const int n = blockIdx.x, tid = threadIdx.x;
    const float s0 = g_scores[n * T_S + tid];
    const float s1 = g_scores[n * T_S + 1024 + tid];

    float m = fmaxf(s0, s1);
#pragma unroll
    for (int o = 16; o > 0; o >>= 1) m = fmaxf(m, __shfl_xor_sync(~0u, m, o));
    if ((tid & 31) == 0) red[tid >> 5] = m;
    __syncthreads();
    if (tid < 32) {
        float x = red[tid];
#pragma unroll
        for (int o = 16; o > 0; o >>= 1) x = fmaxf(x, __shfl_xor_sync(~0u, x, o));
        if (tid == 0) red[0] = x;
    }
    __syncthreads();
    const float M = red[0];
    __syncthreads();

    const float e0 = __expf(s0 - M), e1 = __expf(s1 - M);
    float s = e0 + e1;
#pragma unroll
    for (int o = 16; o > 0; o >>= 1) s += __shfl_xor_sync(~0u, s, o);
    if ((tid & 31) == 0) red[tid >> 5] = s;
    __syncthreads();
    if (tid < 32) {
        float x = red[tid];
#pragma unroll
        for (int o = 16; o > 0; o >>= 1) x += __shfl_xor_sync(~0u, x, o);
        if (tid == 0) red[0] = x;
    }
    __syncthreads();
    const float inv = 1.0f / red[0];
    g_weights[n * T_S + tid] = e0 * inv;
    g_weights[n * T_S + 1024 + tid] = e1 * inv;
}

// ---------------------------------------------------------------------------
// Launch 5: context[n,h] = sum_t w[n,t]*gruH[n,t,h] (fp16 reads, fp32 accum)
// grid (32, 8), block 128; each thread handles 8 h-columns over 256 t
// ---------------------------------------------------------------------------
__global__ void context_kernel(float* __restrict__ out) {
    __shared__ float sw[256];
    const int n = blockIdx.x, tc = blockIdx.y;
    const int tid = threadIdx.x;
    const int t0 = tc * 256;
    sw[tid] = g_weights[n * T_S + t0 + tid];
    sw[tid + 128] = g_weights[n * T_S + t0 + tid + 128];
    __syncthreads();

    const int h = tid * 8;
    const __half* g = g_gruH + ((size_t)n * T_S + t0) * H_S + h;
    float acc[8] = {0.f, 0.f, 0.f, 0.f, 0.f, 0.f, 0.f, 0.f};
#pragma unroll 4
    for (int t = 0; t < 256; t++) {
        const uint4 raw = *(const uint4*)(g + (size_t)t * H_S);
        const __half2* hp = (const __half2*)&raw;
        const float w = sw[t];
#pragma unroll
        for (int q = 0; q < 4; q++) {
            const float2 f = __half22float2(hp[q]);
            acc[2 * q + 0] = fmaf(w, f.x, acc[2 * q + 0]);
            acc[2 * q + 1] = fmaf(w, f.y, acc[2 * q + 1]);
        }
    }
#pragma unroll
    for (int q = 0; q < 8; q++)
        atomicAdd(&out[n * H_S + h + q], acc[q]);
}

// ---------------------------------------------------------------------------
extern "C" void kernel_launch(void* const* d_in, const int* in_sizes, int n_in,
                              void* d_out, int out_size) {
    const float* gru  = (const float*)d_in[0];  // (32, 2048, 1024)
    const float* cond = (const float*)d_in[1];  // (32, 384)
    const float* Wh   = (const float*)d_in[2];  // (1024, 1024)
    const float* Wc   = (const float*)d_in[3];  // (384, 1024)
    const float* bias = (const float*)d_in[4];  // (1024,)
    const float* v    = (const float*)d_in[5];  // (1024,)
    float* out = (float*)d_out;                 // (32, 1024)

    static bool attr_done = false;
    if (!attr_done) {
        cudaFuncSetAttribute(gemm_scores_mma,
                             cudaFuncAttributeMaxDynamicSharedMemorySize, SMEM_TOT);
        attr_done = true;
    }

    convert_gru_kernel<<<32768, 256>>>(gru);
    prep_kernel<<<dim3(32, 4), 256>>>(cond, Wc, bias, out);
    transpose_wh<<<dim3(32, 32), dim3(32, 8)>>>(Wh);
    gemm_scores_mma<<<dim3(8, 512), 256, SMEM_TOT>>>(v);
    softmax_kernel<<<32, 1024>>>();
    context_kernel<<<dim3(32, 8), 128>>>(out);
}

// round 11
// speedup vs baseline: 2.9613x; 1.2660x over previous
#include <cuda_runtime.h>
#include <cuda_fp16.h>
#include <cstdint>
#include <math.h>

#define N_B 32
#define T_S 2048
#define H_S 1024
#define D_S 384
#define ROWS (N_B * T_S)   // 65536

// scratch (no allocations allowed)
__device__ float g_cb[N_B * H_S];        // c_proj + bias
__device__ float g_scores[ROWS];
__device__ float g_weights[ROWS];
__device__ __half g_WhTH[H_S * H_S];     // WhT[c][k] = Wh[k][c], fp16
__device__ __half g_gruH[(size_t)ROWS * H_S];  // gru in fp16 (134 MB)

// ---------------------------------------------------------------------------
// helpers
// ---------------------------------------------------------------------------
__device__ __forceinline__ uint32_t smem_u32(const void* p) {
    uint32_t a;
    asm("{ .reg .u64 t; cvta.to.shared.u64 t, %1; cvt.u32.u64 %0, t; }" : "=r"(a) : "l"(p));
    return a;
}
__device__ __forceinline__ float tanha(float x) {
    asm("tanh.approx.f32 %0, %0;" : "+f"(x));
    return x;
}
__device__ __forceinline__ void cp_async16(uint32_t dst, const void* src) {
    asm volatile("cp.async.cg.shared.global [%0], [%1], 16;" :: "r"(dst), "l"(src) : "memory");
}
__device__ __forceinline__ void ldmx4(uint32_t r[4], uint32_t addr) {
    asm volatile("ldmatrix.sync.aligned.m8n8.x4.shared.b16 {%0,%1,%2,%3}, [%4];"
                 : "=r"(r[0]), "=r"(r[1]), "=r"(r[2]), "=r"(r[3]) : "r"(addr));
}
__device__ __forceinline__ void mma16(float c[4], const uint32_t a[4], uint32_t b0, uint32_t b1) {
    asm volatile(
        "mma.sync.aligned.m16n8k16.row.col.f32.f16.f16.f32 "
        "{%0,%1,%2,%3}, {%4,%5,%6,%7}, {%8,%9}, {%0,%1,%2,%3};\n"
        : "+f"(c[0]), "+f"(c[1]), "+f"(c[2]), "+f"(c[3])
        : "r"(a[0]), "r"(a[1]), "r"(a[2]), "r"(a[3]), "r"(b0), "r"(b1));
}

// ---------------------------------------------------------------------------
// Launch 0: convert gru fp32 -> fp16. 8 floats per thread. grid 32768 x 256
// ---------------------------------------------------------------------------
__global__ void convert_gru_kernel(const float* __restrict__ g) {
    const size_t i = ((size_t)blockIdx.x * 256 + threadIdx.x) * 8;
    const float4 x0 = *(const float4*)(g + i);
    const float4 x1 = *(const float4*)(g + i + 4);
    __half2 h[4];
    h[0] = __floats2half2_rn(x0.x, x0.y);
    h[1] = __floats2half2_rn(x0.z, x0.w);
    h[2] = __floats2half2_rn(x1.x, x1.y);
    h[3] = __floats2half2_rn(x1.z, x1.w);
    *(uint4*)(g_gruH + i) = *(uint4*)h;
}

// ---------------------------------------------------------------------------
// Launch 1: cb[n][k] = bias[k] + cond[n]·Wc[:,k]; zero scores, out
// ---------------------------------------------------------------------------
__global__ void prep_kernel(const float* __restrict__ cond,
                            const float* __restrict__ Wc,
                            const float* __restrict__ bias,
                            float* __restrict__ out) {
    const int n = blockIdx.x;
    const int k = blockIdx.y * 256 + threadIdx.x;
    float acc = bias[k];
    const float* cp = cond + n * D_S;
#pragma unroll 16
    for (int d = 0; d < D_S; d++)
        acc = fmaf(cp[d], Wc[d * H_S + k], acc);
    g_cb[n * H_S + k] = acc;
    out[n * H_S + k] = 0.0f;
    g_scores[n * T_S + blockIdx.y * 512 + threadIdx.x] = 0.0f;
    g_scores[n * T_S + blockIdx.y * 512 + threadIdx.x + 256] = 0.0f;
}

// ---------------------------------------------------------------------------
// Launch 2: transpose Wh -> g_WhTH (fp16). grid (32,32), block (32,8)
// ---------------------------------------------------------------------------
__global__ void transpose_wh(const float* __restrict__ Wh) {
    __shared__ float t[32][33];
    const int c0 = blockIdx.x * 32, k0 = blockIdx.y * 32;
    const int tx = threadIdx.x, ty = threadIdx.y;
#pragma unroll
    for (int i = 0; i < 4; i++)
        t[ty + 8 * i][tx] = Wh[(size_t)(k0 + ty + 8 * i) * H_S + c0 + tx];
    __syncthreads();
#pragma unroll
    for (int i = 0; i < 4; i++)
        g_WhTH[(size_t)(c0 + ty + 8 * i) * H_S + k0 + tx] = __float2half_rn(t[tx][ty + 8 * i]);
}

// ---------------------------------------------------------------------------
// Launch 3: fp16 m16n8k16 GEMM 128x128x1024 per CTA + fused v·tanh epilogue
// BK=64, 3-stage cp.async (issue split across ks blocks), 2 CTAs/SM.
// grid (8 col-chunks, 512 row-tiles), block 256 (8 warps, 4x2 warp grid)
// ---------------------------------------------------------------------------
#define BK 64
#define KT (H_S / BK)        // 16
#define RB 144               // smem row stride bytes (128B data + 16B pad)
#define A_BYTES (128 * RB)   // 18432
#define B_BYTES (128 * RB)   // 18432
#define STG_BYTES (A_BYTES + B_BYTES)  // 36864
#define NST 3
#define VCB_OFF (NST * STG_BYTES)      // 110592
#define SMEM_TOT (VCB_OFF + 128 * 8)   // 111616

__global__ __launch_bounds__(256, 2) void gemm_scores_mma(
    const float* __restrict__ v) {
    extern __shared__ __align__(128) char smem[];
    const uint32_t sb = smem_u32(smem);
    float2* vcb = (float2*)(smem + VCB_OFF);

    const int tid = threadIdx.x, wid = tid >> 5, lane = tid & 31;
    const int colBase = blockIdx.x * 128;
    const int rowBase = blockIdx.y * 128;
    const int n = rowBase >> 11;   // 128-row tiles never straddle a batch

    if (tid < 128)
        vcb[tid] = make_float2(v[colBase + tid], g_cb[n * H_S + colBase + tid]);

    // --- gmem -> smem: per stage, A = 4 x 16B, B = 4 x 16B per thread
    const int lr = tid >> 3;          // row 0..31 (+32i)
    const int lcc = tid & 7;          // 16B chunk within 128B row
    const __half* srcA = g_gruH + (size_t)(rowBase + lr) * H_S + lcc * 8;
    const __half* srcB = g_WhTH + (size_t)(colBase + lr) * H_S + lcc * 8;
    const uint32_t dA = (uint32_t)(lr * RB + lcc * 16);

    // --- warp tile: rows 32*(wid&3), cols 64*(wid>>2)
    const int rows0 = (wid & 3) * 32;
    const int cols0 = (wid >> 2) * 64;
    const int sel = lane >> 3, j = lane & 7;
    const uint32_t aOff = (uint32_t)((rows0 + (sel & 1) * 8 + j) * RB + (sel >> 1) * 16);
    const uint32_t bOff = (uint32_t)((cols0 + (sel >> 1) * 8 + j) * RB + (sel & 1) * 16);

    float acc[2][8][4];
#pragma unroll
    for (int i = 0; i < 2; i++)
#pragma unroll
        for (int f = 0; f < 8; f++)
#pragma unroll
            for (int q = 0; q < 4; q++) acc[i][f][q] = 0.0f;

    auto issueA = [&](int s, int kc) {
        const uint32_t sa = sb + s * STG_BYTES;
        const __half* pa = srcA + kc * BK;
#pragma unroll
        for (int i = 0; i < 4; i++)
            cp_async16(sa + dA + i * (32 * RB), pa + (size_t)(32 * i) * H_S);
    };
    auto issueB = [&](int s, int kc) {
        const uint32_t sbb = sb + s * STG_BYTES + A_BYTES;
        const __half* pb = srcB + kc * BK;
#pragma unroll
        for (int i = 0; i < 4; i++)
            cp_async16(sbb + dA + i * (32 * RB), pb + (size_t)(32 * i) * H_S);
        asm volatile("cp.async.commit_group;" ::: "memory");
    };

    issueA(0, 0); issueB(0, 0);
    issueA(1, 1); issueB(1, 1);

#pragma unroll 1
    for (int kc = 0; kc < KT; kc++) {
        if (kc + 1 < KT)
            asm volatile("cp.async.wait_group 1;" ::: "memory");
        else
            asm volatile("cp.async.wait_group 0;" ::: "memory");
        __syncthreads();

        const uint32_t base = sb + (kc % NST) * STG_BYTES;
        const uint32_t Ab = base + aOff;
        const uint32_t Bb = base + A_BYTES + bOff;
        const bool pre = (kc + 2 < KT);
        const int ps = (kc + 2) % NST;

#pragma unroll
        for (int ks = 0; ks < 4; ks++) {   // 4 k-steps of 16 halves (32B each)
            uint32_t af[2][4], bf[4][4];
#pragma unroll
            for (int mf = 0; mf < 2; mf++)
                ldmx4(af[mf], Ab + mf * (16 * RB) + ks * 32);
#pragma unroll
            for (int nb = 0; nb < 4; nb++)
                ldmx4(bf[nb], Bb + nb * (16 * RB) + ks * 32);
#pragma unroll
            for (int nb = 0; nb < 4; nb++) {
                mma16(acc[0][2 * nb + 0], af[0], bf[nb][0], bf[nb][1]);
                mma16(acc[1][2 * nb + 0], af[1], bf[nb][0], bf[nb][1]);
                mma16(acc[0][2 * nb + 1], af[0], bf[nb][2], bf[nb][3]);
                mma16(acc[1][2 * nb + 1], af[1], bf[nb][2], bf[nb][3]);
            }
            // spread next-stage loads into the MMA-rich region
            if (ks == 0 && pre) issueA(ps, kc + 2);
            if (ks == 1 && pre) issueB(ps, kc + 2);
        }
    }

    // --- epilogue: partial score = sum_cols v[c] * tanh(hp + cb[c])
    float part[2][2] = {{0.0f, 0.0f}, {0.0f, 0.0f}};
#pragma unroll
    for (int mf = 0; mf < 2; mf++)
#pragma unroll
        for (int nf = 0; nf < 8; nf++) {
            const int c = cols0 + nf * 8 + 2 * (lane & 3);
            const float2 vc0 = vcb[c], vc1 = vcb[c + 1];
            part[mf][0] += vc0.x * tanha(acc[mf][nf][0] + vc0.y)
                         + vc1.x * tanha(acc[mf][nf][1] + vc1.y);
            part[mf][1] += vc0.x * tanha(acc[mf][nf][2] + vc0.y)
                         + vc1.x * tanha(acc[mf][nf][3] + vc1.y);
        }

#pragma unroll
    for (int mf = 0; mf < 2; mf++)
#pragma unroll
        for (int rh = 0; rh < 2; rh++) {
            float p = part[mf][rh];
            p += __shfl_xor_sync(0xffffffffu, p, 1);
            p += __shfl_xor_sync(0xffffffffu, p, 2);
            if ((lane & 3) == 0) {
                const int row = rowBase + rows0 + mf * 16 + rh * 8 + (lane >> 2);
                atomicAdd(&g_scores[row], p);
            }
        }
}

// ---------------------------------------------------------------------------
// Launch 4: softmax over T per batch. grid 32, block 1024
// ---------------------------------------------------------------------------
__global__ void softmax_kernel() {
    __shared__ float red[32];
    const int n = blockIdx.x, tid = threadIdx.x;
    const float s0 = g_scores[n * T_S + tid];
    const float s1 = g_scores[n * T_S + 1024 + tid];

    float m = fmaxf(s0, s1);
#pragma unroll
    for (int o = 16; o > 0; o >>= 1) m = fmaxf(m, __shfl_xor_sync(~0u, m, o));
    if ((tid & 31) == 0) red[tid >> 5] = m;
    __syncthreads();
    if (tid < 32) {
        float x = red[tid];
#pragma unroll
        for (int o = 16; o > 0; o >>= 1) x = fmaxf(x, __shfl_xor_sync(~0u, x, o));
        if (tid == 0) red[0] = x;
    }
    __syncthreads();
    const float M = red[0];
    __syncthreads();

    const float e0 = __expf(s0 - M), e1 = __expf(s1 - M);
    float s = e0 + e1;
#pragma unroll
    for (int o = 16; o > 0; o >>= 1) s += __shfl_xor_sync(~0u, s, o);
    if ((tid & 31) == 0) red[tid >> 5] = s;
    __syncthreads();
    if (tid < 32) {
        float x = red[tid];
#pragma unroll
        for (int o = 16; o > 0; o >>= 1) x += __shfl_xor_sync(~0u, x, o);
        if (tid == 0) red[0] = x;
    }
    __syncthreads();
    const float inv = 1.0f / red[0];
    g_weights[n * T_S + tid] = e0 * inv;
    g_weights[n * T_S + 1024 + tid] = e1 * inv;
}

// ---------------------------------------------------------------------------
// Launch 5: context[n,h] = sum_t w[n,t]*gruH[n,t,h] (fp16 reads, fp32 accum)
// grid (32, 16), block 128; 8 h-cols per thread, 128 t per chunk
// ---------------------------------------------------------------------------
__global__ void context_kernel(float* __restrict__ out) {
    __shared__ float sw[128];
    const int n = blockIdx.x, tc = blockIdx.y;
    const int tid = threadIdx.x;
    const int t0 = tc * 128;
    sw[tid] = g_weights[n * T_S + t0 + tid];
    __syncthreads();

    const int h = tid * 8;
    const __half* g = g_gruH + ((size_t)n * T_S + t0) * H_S + h;
    float acc[8] = {0.f, 0.f, 0.f, 0.f, 0.f, 0.f, 0.f, 0.f};
#pragma unroll 8
    for (int t = 0; t < 128; t++) {
        const uint4 raw = *(const uint4*)(g + (size_t)t * H_S);
        const __half2* hp = (const __half2*)&raw;
        const float w = sw[t];
#pragma unroll
        for (int q = 0; q < 4; q++) {
            const float2 f = __half22float2(hp[q]);
            acc[2 * q + 0] = fmaf(w, f.x, acc[2 * q + 0]);
            acc[2 * q + 1] = fmaf(w, f.y, acc[2 * q + 1]);
        }
    }
#pragma unroll
    for (int q = 0; q < 8; q++)
        atomicAdd(&out[n * H_S + h + q], acc[q]);
}

// ---------------------------------------------------------------------------
extern "C" void kernel_launch(void* const* d_in, const int* in_sizes, int n_in,
                              void* d_out, int out_size) {
    const float* gru  = (const float*)d_in[0];  // (32, 2048, 1024)
    const float* cond = (const float*)d_in[1];  // (32, 384)
    const float* Wh   = (const float*)d_in[2];  // (1024, 1024)
    const float* Wc   = (const float*)d_in[3];  // (384, 1024)
    const float* bias = (const float*)d_in[4];  // (1024,)
    const float* v    = (const float*)d_in[5];  // (1024,)
    float* out = (float*)d_out;                 // (32, 1024)

    static bool attr_done = false;
    if (!attr_done) {
        cudaFuncSetAttribute(gemm_scores_mma,
                             cudaFuncAttributeMaxDynamicSharedMemorySize, SMEM_TOT);
        attr_done = true;
    }

    convert_gru_kernel<<<32768, 256>>>(gru);
    prep_kernel<<<dim3(32, 4), 256>>>(cond, Wc, bias, out);
    transpose_wh<<<dim3(32, 32), dim3(32, 8)>>>(Wh);
    gemm_scores_mma<<<dim3(8, 512), 256, SMEM_TOT>>>(v);
    softmax_kernel<<<32, 1024>>>();
    context_kernel<<<dim3(32, 16), 128>>>(out);
}